// round 5
// baseline (speedup 1.0000x reference)
#include <cuda_runtime.h>
#include <cuda_bf16.h>
#include <math.h>
#include <stdint.h>

#define PITCH 136                 // bf16 elements per smem row (272B)
#define BUFP  132                 // fp32 exchange buffer pitch (floats)

// ---- smem layout (byte offsets) ----
#define XH_OFF  0                 // X hi -> V hi
#define XL_OFF  34816             // X lo -> V lo
#define KH_OFF  69632             // Wk hi -> K hi -> P hi
#define KL_OFF  104448            // Wk lo -> K lo -> P lo
#define WH_OFF  139264            // Wq hi -> Wvo hi
#define WL_OFF  174080            // Wq lo -> Wvo lo
#define BUF_OFF 139264            // fp32 exchange buffer (overlays W, 67584B)
#define GB_OFF  208896            // gamma, beta, gelu(beta): 3*128 floats
#define SMEM_BYTES 210432

// ---- global scratch ----
__device__ float g_Wvo[128 * 128];
__device__ __align__(16) unsigned short g_wh[3][128 * PITCH];  // [n][k] hi
__device__ __align__(16) unsigned short g_wl[3][128 * PITCH];  // [n][k] lo

// ---------------------------------------------------------------------------
static __device__ __forceinline__ uint32_t smem_u32(const void* p) {
    uint32_t a;
    asm("{ .reg .u64 t; cvta.to.shared.u64 t, %1; cvt.u32.u64 %0, t; }"
        : "=r"(a) : "l"(p));
    return a;
}
static __device__ __forceinline__ void cp16(uint32_t dst, const void* src) {
    asm volatile("cp.async.cg.shared.global [%0], [%1], 16;"
                 :: "r"(dst), "l"(src) : "memory");
}
#define CP_COMMIT() asm volatile("cp.async.commit_group;" ::: "memory")
#define CP_WAIT0()  asm volatile("cp.async.wait_group 0;" ::: "memory")

static __device__ __forceinline__ void split2(float a, float b,
                                              uint32_t& hi, uint32_t& lo) {
    __nv_bfloat16 ha = __float2bfloat16(a), hb = __float2bfloat16(b);
    float ra = a - __bfloat162float(ha);
    float rb = b - __bfloat162float(hb);
    __nv_bfloat16 la = __float2bfloat16(ra), lb = __float2bfloat16(rb);
    hi = ((uint32_t)__bfloat16_as_ushort(hb) << 16) | __bfloat16_as_ushort(ha);
    lo = ((uint32_t)__bfloat16_as_ushort(lb) << 16) | __bfloat16_as_ushort(la);
}
static __device__ __forceinline__ void mma_bf16(float c[4], uint32_t a0,
                                                uint32_t a1, uint32_t a2,
                                                uint32_t a3, uint32_t b0,
                                                uint32_t b1) {
    asm volatile(
        "mma.sync.aligned.m16n8k16.row.col.f32.bf16.bf16.f32 "
        "{%0,%1,%2,%3}, {%4,%5,%6,%7}, {%8,%9}, {%0,%1,%2,%3};"
        : "+f"(c[0]), "+f"(c[1]), "+f"(c[2]), "+f"(c[3])
        : "r"(a0), "r"(a1), "r"(a2), "r"(a3), "r"(b0), "r"(b1));
}
static __device__ __forceinline__ void ldsm4(uint32_t& r0, uint32_t& r1,
                                             uint32_t& r2, uint32_t& r3,
                                             uint32_t addr) {
    asm volatile("ldmatrix.sync.aligned.m8n8.x4.shared.b16 {%0,%1,%2,%3}, [%4];"
                 : "=r"(r0), "=r"(r1), "=r"(r2), "=r"(r3) : "r"(addr));
}
static __device__ __forceinline__ void ldsm4t(uint32_t& r0, uint32_t& r1,
                                              uint32_t& r2, uint32_t& r3,
                                              uint32_t addr) {
    asm volatile(
        "ldmatrix.sync.aligned.m8n8.x4.trans.shared.b16 {%0,%1,%2,%3}, [%4];"
        : "=r"(r0), "=r"(r1), "=r"(r2), "=r"(r3) : "r"(addr));
}

// 3-pass MMA bundle for an acc-pair: hi*bhi + hi*blo + lo*bhi
static __device__ __forceinline__ void mma_jp(float a0[4], float a1[4],
                                              const uint32_t ah[4],
                                              const uint32_t al[4],
                                              uint32_t b0, uint32_t b1,
                                              uint32_t b2, uint32_t b3,
                                              uint32_t c0, uint32_t c1,
                                              uint32_t c2, uint32_t c3) {
    mma_bf16(a0, ah[0], ah[1], ah[2], ah[3], b0, b1);
    mma_bf16(a1, ah[0], ah[1], ah[2], ah[3], b2, b3);
    mma_bf16(a0, ah[0], ah[1], ah[2], ah[3], c0, c1);
    mma_bf16(a1, ah[0], ah[1], ah[2], ah[3], c2, c3);
    mma_bf16(a0, al[0], al[1], al[2], al[3], b0, b1);
    mma_bf16(a1, al[0], al[1], al[2], al[3], b2, b3);
}

// N-split GEMM: acc2[8][4] = X-rows(16) @ W cols [64h, 64h+64)
static __device__ __forceinline__ void gemm_half(uint32_t aH, uint32_t aL,
                                                 uint32_t bH, uint32_t bL,
                                                 int h, float acc2[8][4]) {
#pragma unroll
    for (int j = 0; j < 8; ++j)
#pragma unroll
        for (int i = 0; i < 4; ++i) acc2[j][i] = 0.f;
#pragma unroll
    for (int kk = 0; kk < 8; ++kk) {
        uint32_t ah[4], al[4];
        ldsm4(ah[0], ah[1], ah[2], ah[3], aH + kk * 32);
        ldsm4(al[0], al[1], al[2], al[3], aL + kk * 32);
#pragma unroll
        for (int jl = 0; jl < 4; ++jl) {
            uint32_t o = (uint32_t)((4 * h + jl) * 16 * PITCH + kk * 16) * 2;
            uint32_t b0, b1, b2, b3, c0, c1, c2, c3;
            ldsm4(b0, b1, b2, b3, bH + o);
            ldsm4(c0, c1, c2, c3, bL + o);
            mma_jp(acc2[2 * jl], acc2[2 * jl + 1], ah, al, b0, b1, b2, b3, c0,
                   c1, c2, c3);
        }
    }
}

// k-split S GEMM: acc[16][4] partial = A-frags(k-half h) @ K^T(full 128 n)
static __device__ __forceinline__ void gemm_S(const uint32_t* Ah,
                                              const uint32_t* Al, uint32_t bH,
                                              uint32_t bL, int h,
                                              float acc[16][4]) {
#pragma unroll
    for (int j = 0; j < 16; ++j)
#pragma unroll
        for (int i = 0; i < 4; ++i) acc[j][i] = 0.f;
#pragma unroll
    for (int kkl = 0; kkl < 4; ++kkl) {
#pragma unroll
        for (int jp = 0; jp < 8; ++jp) {
            uint32_t o =
                (uint32_t)(jp * 16 * PITCH + (4 * h + kkl) * 16) * 2;
            uint32_t b0, b1, b2, b3, c0, c1, c2, c3;
            ldsm4(b0, b1, b2, b3, bH + o);
            ldsm4(c0, c1, c2, c3, bL + o);
            mma_jp(acc[2 * jp], acc[2 * jp + 1], &Ah[4 * kkl], &Al[4 * kkl],
                   b0, b1, b2, b3, c0, c1, c2, c3);
        }
    }
}

// k-split H GEMM: acc[16][4] partial = P-frags(k-half h) @ V (trans B)
static __device__ __forceinline__ void gemm_H(const uint32_t* Ah,
                                              const uint32_t* Al, uint32_t xH,
                                              uint32_t xL, int h,
                                              float acc[16][4]) {
#pragma unroll
    for (int j = 0; j < 16; ++j)
#pragma unroll
        for (int i = 0; i < 4; ++i) acc[j][i] = 0.f;
#pragma unroll
    for (int kkl = 0; kkl < 4; ++kkl) {
#pragma unroll
        for (int jp = 0; jp < 8; ++jp) {
            uint32_t o =
                (uint32_t)((4 * h + kkl) * 16 * PITCH + jp * 16) * 2;
            uint32_t b0, b1, b2, b3, c0, c1, c2, c3;
            ldsm4t(b0, b1, b2, b3, xH + o);
            ldsm4t(c0, c1, c2, c3, xL + o);
            mma_jp(acc[2 * jp], acc[2 * jp + 1], &Ah[4 * kkl], &Al[4 * kkl],
                   b0, b1, b2, b3, c0, c1, c2, c3);
        }
    }
}

// acc2 -> A-frags for the k-half owned by this warp
static __device__ __forceinline__ void to_afrag8(const float acc2[8][4],
                                                 uint32_t* Ah, uint32_t* Al) {
#pragma unroll
    for (int k = 0; k < 4; ++k) {
        split2(acc2[2 * k][0], acc2[2 * k][1], Ah[4 * k + 0], Al[4 * k + 0]);
        split2(acc2[2 * k][2], acc2[2 * k][3], Ah[4 * k + 1], Al[4 * k + 1]);
        split2(acc2[2 * k + 1][0], acc2[2 * k + 1][1], Ah[4 * k + 2],
               Al[4 * k + 2]);
        split2(acc2[2 * k + 1][2], acc2[2 * k + 1][3], Ah[4 * k + 3],
               Al[4 * k + 3]);
    }
}

// store N-split result (16 rows x 64 cols at col base 64h) as bf16 hi/lo
static __device__ __forceinline__ void store_half(const float acc2[8][4],
                                                  unsigned short* H,
                                                  unsigned short* L, int R,
                                                  int g, int t, int h) {
#pragma unroll
    for (int j = 0; j < 8; ++j) {
        const int col = 64 * h + 8 * j + 2 * t;
        uint32_t hh, ll;
        split2(acc2[j][0], acc2[j][1], hh, ll);
        *(uint32_t*)&H[(R + g) * PITCH + col] = hh;
        *(uint32_t*)&L[(R + g) * PITCH + col] = ll;
        split2(acc2[j][2], acc2[j][3], hh, ll);
        *(uint32_t*)&H[(R + g + 8) * PITCH + col] = hh;
        *(uint32_t*)&L[(R + g + 8) * PITCH + col] = ll;
    }
}

// ---------------------------------------------------------------------------
__global__ void wvo_kernel(const float* __restrict__ Wv,
                           const float* __restrict__ Wo) {
    __shared__ float wv[128];
    int r = blockIdx.x, n = threadIdx.x;
    wv[n] = Wv[r * 128 + n];
    __syncthreads();
    float acc = 0.f;
#pragma unroll 8
    for (int k = 0; k < 128; ++k) acc = fmaf(wv[k], Wo[k * 128 + n], acc);
    g_Wvo[r * 128 + n] = acc;
}

__global__ void prep_kernel(const float* __restrict__ Wq,
                            const float* __restrict__ Wk) {
    int m = blockIdx.x, n = threadIdx.x;
    const float* src = (m == 0) ? Wq : (m == 1) ? Wk : g_Wvo;
    float scale = (m == 0) ? 0.08838834764831845f : 1.0f;
    for (int k = 0; k < 128; ++k) {
        float w = src[k * 128 + n] * scale;
        __nv_bfloat16 h = __float2bfloat16(w);
        float r = w - __bfloat162float(h);
        __nv_bfloat16 l = __float2bfloat16(r);
        g_wh[m][n * PITCH + k] = __bfloat16_as_ushort(h);
        g_wl[m][n * PITCH + k] = __bfloat16_as_ushort(l);
    }
}

// ---------------------------------------------------------------------------
// Fused kernel: one CTA per 128-token block, 512 threads (16 warps).
// Warp pair (w, w+8) owns rows [16*(w&7), +16); h = w>>3 is the N/k half.
// Also stores the mirrored zeros-passer block: gelu(beta) broadcast.
// ---------------------------------------------------------------------------
__global__ void __launch_bounds__(512, 1) attn_kernel(
    const float* __restrict__ x, const float* __restrict__ gamma,
    const float* __restrict__ beta, float* __restrict__ out) {
    extern __shared__ char smc[];
    const int tid = threadIdx.x;
    const int lane = tid & 31;
    const int w = tid >> 5;
    const int g = lane >> 2, t = lane & 3;
    const int rowg = w & 7, h = w >> 3;
    const int R = 16 * rowg;

    const uint32_t xh_u = smem_u32(smc + XH_OFF);
    const uint32_t xl_u = smem_u32(smc + XL_OFF);
    const uint32_t kh_u = smem_u32(smc + KH_OFF);
    const uint32_t kl_u = smem_u32(smc + KL_OFF);
    const uint32_t wh_u = smem_u32(smc + WH_OFF);
    const uint32_t wl_u = smem_u32(smc + WL_OFF);

    const int L = lane;
    const uint32_t offA =
        (uint32_t)(((L & 7) + (L & 8)) * PITCH + ((L & 16) ? 8 : 0)) * 2;
    const uint32_t offB =
        (uint32_t)(((L & 7) + ((L & 16) ? 8 : 0)) * PITCH + (L & 8)) * 2;
    const uint32_t offT =
        (uint32_t)((L & 15) * PITCH + ((L & 16) ? 8 : 0)) * 2;

    // --- prefetch Wq -> W region, Wk -> K region ---
    for (int i = tid; i < 2176; i += 512) {
        cp16(wh_u + i * 16, (const char*)g_wh[0] + i * 16);
        cp16(wl_u + i * 16, (const char*)g_wl[0] + i * 16);
        cp16(kh_u + i * 16, (const char*)g_wh[1] + i * 16);
        cp16(kl_u + i * 16, (const char*)g_wl[1] + i * 16);
    }
    CP_COMMIT();

    float* sgam = (float*)(smc + GB_OFF);
    float* sbet = sgam + 128;
    float* sgel = sgam + 256;
    if (tid < 128) {
        float b = beta[tid];
        sgam[tid] = gamma[tid];
        sbet[tid] = b;
        sgel[tid] = 0.5f * b * (1.f + erff(b * 0.70710678118654752f));
    }

    // --- load X tile -> bf16 hi/lo smem ---
    const int xrow = tid >> 2, xc0 = (tid & 3) * 32;
    {
        unsigned short* XH = (unsigned short*)(smc + XH_OFF);
        unsigned short* XL = (unsigned short*)(smc + XL_OFF);
        const long long base =
            ((long long)blockIdx.y * 8192 + (long long)blockIdx.x * 128) * 128;
        const float4* xg = (const float4*)(x + base + xrow * 128 + xc0);
#pragma unroll
        for (int i = 0; i < 8; ++i) {
            float4 f = xg[i];
            uint32_t h0, l0, h1, l1;
            split2(f.x, f.y, h0, l0);
            split2(f.z, f.w, h1, l1);
            *(uint32_t*)&XH[xrow * PITCH + xc0 + 4 * i] = h0;
            *(uint32_t*)&XH[xrow * PITCH + xc0 + 4 * i + 2] = h1;
            *(uint32_t*)&XL[xrow * PITCH + xc0 + 4 * i] = l0;
            *(uint32_t*)&XL[xrow * PITCH + xc0 + 4 * i + 2] = l1;
        }
    }
    CP_WAIT0();
    __syncthreads();

    // --- zeros-passer mirror block: out2 = gelu(beta) broadcast ---
    {
        float* o2 = out + (long long)blockIdx.y * 16384 * 128 +
                    ((long long)8192 + blockIdx.x * 128 + xrow) * 128 + xc0;
#pragma unroll
        for (int i = 0; i < 8; ++i)
            *(float4*)(o2 + 4 * i) =
                make_float4(sgel[xc0 + 4 * i], sgel[xc0 + 4 * i + 1],
                            sgel[xc0 + 4 * i + 2], sgel[xc0 + 4 * i + 3]);
    }

    float acc2[8][4];
    uint32_t Ah[16], Al[16];
    const uint32_t aH = xh_u + (uint32_t)(R * PITCH) * 2 + offA;
    const uint32_t aL = xl_u + (uint32_t)(R * PITCH) * 2 + offA;

    // ---- Q = X @ Wq' (N-split) ----
    gemm_half(aH, aL, wh_u + offB, wl_u + offB, h, acc2);
    to_afrag8(acc2, Ah, Al);  // Q frags for k-half h
    __syncthreads();          // Wq reads done

    // prefetch Wvo -> W region (overlaps K GEMM)
    for (int i = tid; i < 2176; i += 512) {
        cp16(wh_u + i * 16, (const char*)g_wh[2] + i * 16);
        cp16(wl_u + i * 16, (const char*)g_wl[2] + i * 16);
    }
    CP_COMMIT();

    // ---- K = X @ Wk (N-split, Wk staged in K region) ----
    gemm_half(aH, aL, kh_u + offB, kl_u + offB, h, acc2);
    __syncthreads();  // all Wk reads done
    store_half(acc2, (unsigned short*)(smc + KH_OFF),
               (unsigned short*)(smc + KL_OFF), R, g, t, h);
    CP_WAIT0();
    __syncthreads();  // K visible, Wvo ready

    // ---- V = X @ Wvo (N-split) ----
    gemm_half(aH, aL, wh_u + offB, wl_u + offB, h, acc2);
    __syncthreads();  // all X reads done (V GEMM was the last reader)
    store_half(acc2, (unsigned short*)(smc + XH_OFF),
               (unsigned short*)(smc + XL_OFF), R, g, t, h);
    // (V visibility for H GEMM is guaranteed by the exchange barriers below)

    // ---- S partial = Q(k-half) @ K^T ----
    float acc[16][4];
    gemm_S(Ah, Al, kh_u + offB, kl_u + offB, h, acc);

    float* buf = (float*)(smc + BUF_OFF);
    if (h == 0) {
#pragma unroll
        for (int j = 0; j < 16; ++j) {
            const int col = 8 * j + 2 * t;
            *(float2*)&buf[(R + g) * BUFP + col] =
                make_float2(acc[j][0], acc[j][1]);
            *(float2*)&buf[(R + g + 8) * BUFP + col] =
                make_float2(acc[j][2], acc[j][3]);
        }
    }
    __syncthreads();
    if (h == 1) {
#pragma unroll
        for (int j = 0; j < 16; ++j) {
            const int col = 8 * j + 2 * t;
            float2 u0 = *(float2*)&buf[(R + g) * BUFP + col];
            float2 u1 = *(float2*)&buf[(R + g + 8) * BUFP + col];
            acc[j][0] += u0.x;
            acc[j][1] += u0.y;
            acc[j][2] += u1.x;
            acc[j][3] += u1.y;
        }
        // softmax over full rows
        float mx0 = -1e30f, mx1 = -1e30f;
#pragma unroll
        for (int j = 0; j < 16; ++j) {
            mx0 = fmaxf(mx0, fmaxf(acc[j][0], acc[j][1]));
            mx1 = fmaxf(mx1, fmaxf(acc[j][2], acc[j][3]));
        }
        mx0 = fmaxf(mx0, __shfl_xor_sync(0xffffffffu, mx0, 1));
        mx0 = fmaxf(mx0, __shfl_xor_sync(0xffffffffu, mx0, 2));
        mx1 = fmaxf(mx1, __shfl_xor_sync(0xffffffffu, mx1, 1));
        mx1 = fmaxf(mx1, __shfl_xor_sync(0xffffffffu, mx1, 2));
        float s0 = 0.f, s1 = 0.f;
#pragma unroll
        for (int j = 0; j < 16; ++j) {
            acc[j][0] = __expf(acc[j][0] - mx0);
            acc[j][1] = __expf(acc[j][1] - mx0);
            acc[j][2] = __expf(acc[j][2] - mx1);
            acc[j][3] = __expf(acc[j][3] - mx1);
            s0 += acc[j][0] + acc[j][1];
            s1 += acc[j][2] + acc[j][3];
        }
        s0 += __shfl_xor_sync(0xffffffffu, s0, 1);
        s0 += __shfl_xor_sync(0xffffffffu, s0, 2);
        s1 += __shfl_xor_sync(0xffffffffu, s1, 1);
        s1 += __shfl_xor_sync(0xffffffffu, s1, 2);
        float i0 = 1.0f / s0, i1 = 1.0f / s1;
        unsigned short* PH = (unsigned short*)(smc + KH_OFF);
        unsigned short* PL = (unsigned short*)(smc + KL_OFF);
#pragma unroll
        for (int j = 0; j < 16; ++j) {
            const int col = 8 * j + 2 * t;
            uint32_t hh, ll;
            split2(acc[j][0] * i0, acc[j][1] * i0, hh, ll);
            *(uint32_t*)&PH[(R + g) * PITCH + col] = hh;
            *(uint32_t*)&PL[(R + g) * PITCH + col] = ll;
            split2(acc[j][2] * i1, acc[j][3] * i1, hh, ll);
            *(uint32_t*)&PH[(R + g + 8) * PITCH + col] = hh;
            *(uint32_t*)&PL[(R + g + 8) * PITCH + col] = ll;
        }
    }
    __syncthreads();  // P visible (and V from pre-S writes)

    // ---- H partial = P(k-half) @ V ----
    {
        const uint32_t pH =
            kh_u + (uint32_t)(R * PITCH + 64 * h) * 2 + offA;
        const uint32_t pL =
            kl_u + (uint32_t)(R * PITCH + 64 * h) * 2 + offA;
#pragma unroll
        for (int k = 0; k < 4; ++k) {
            ldsm4(Ah[4 * k], Ah[4 * k + 1], Ah[4 * k + 2], Ah[4 * k + 3],
                  pH + k * 32);
            ldsm4(Al[4 * k], Al[4 * k + 1], Al[4 * k + 2], Al[4 * k + 3],
                  pL + k * 32);
        }
    }
    gemm_H(Ah, Al, xh_u + offT, xl_u + offT, h, acc);

    if (h == 1) {
#pragma unroll
        for (int j = 0; j < 16; ++j) {
            const int col = 8 * j + 2 * t;
            *(float2*)&buf[(R + g) * BUFP + col] =
                make_float2(acc[j][0], acc[j][1]);
            *(float2*)&buf[(R + g + 8) * BUFP + col] =
                make_float2(acc[j][2], acc[j][3]);
        }
    }
    __syncthreads();
    if (h == 0) {
#pragma unroll
        for (int j = 0; j < 16; ++j) {
            const int col = 8 * j + 2 * t;
            float2 u0 = *(float2*)&buf[(R + g) * BUFP + col];
            float2 u1 = *(float2*)&buf[(R + g + 8) * BUFP + col];
            acc[j][0] += u0.x;
            acc[j][1] += u0.y;
            acc[j][2] += u1.x;
            acc[j][3] += u1.y;
        }
        // LayerNorm + exact GELU + store
        float s0 = 0.f, s1 = 0.f;
#pragma unroll
        for (int j = 0; j < 16; ++j) {
            s0 += acc[j][0] + acc[j][1];
            s1 += acc[j][2] + acc[j][3];
        }
        s0 += __shfl_xor_sync(0xffffffffu, s0, 1);
        s0 += __shfl_xor_sync(0xffffffffu, s0, 2);
        s1 += __shfl_xor_sync(0xffffffffu, s1, 1);
        s1 += __shfl_xor_sync(0xffffffffu, s1, 2);
        float mu0 = s0 * (1.0f / 128.0f), mu1 = s1 * (1.0f / 128.0f);
        float q0 = 0.f, q1 = 0.f;
#pragma unroll
        for (int j = 0; j < 16; ++j) {
            float d0 = acc[j][0] - mu0, d1 = acc[j][1] - mu0;
            float d2 = acc[j][2] - mu1, d3 = acc[j][3] - mu1;
            q0 += d0 * d0 + d1 * d1;
            q1 += d2 * d2 + d3 * d3;
        }
        q0 += __shfl_xor_sync(0xffffffffu, q0, 1);
        q0 += __shfl_xor_sync(0xffffffffu, q0, 2);
        q1 += __shfl_xor_sync(0xffffffffu, q1, 1);
        q1 += __shfl_xor_sync(0xffffffffu, q1, 2);
        float r0 = rsqrtf(q0 * (1.0f / 128.0f) + 1e-5f);
        float r1 = rsqrtf(q1 * (1.0f / 128.0f) + 1e-5f);

        float* orow = out + ((long long)blockIdx.y * 16384 +
                             (long long)blockIdx.x * 128 + R + g) * 128;
        float* orow8 = orow + 8 * 128;
#pragma unroll
        for (int j = 0; j < 16; ++j) {
            const int col = 8 * j + 2 * t;
            float ga0 = sgam[col], ga1 = sgam[col + 1];
            float be0 = sbet[col], be1 = sbet[col + 1];
            float y0 = (acc[j][0] - mu0) * r0 * ga0 + be0;
            float y1 = (acc[j][1] - mu0) * r0 * ga1 + be1;
            float y2 = (acc[j][2] - mu1) * r1 * ga0 + be0;
            float y3 = (acc[j][3] - mu1) * r1 * ga1 + be1;
            float2 o0, o1;
            o0.x = 0.5f * y0 * (1.f + erff(y0 * 0.70710678118654752f));
            o0.y = 0.5f * y1 * (1.f + erff(y1 * 0.70710678118654752f));
            o1.x = 0.5f * y2 * (1.f + erff(y2 * 0.70710678118654752f));
            o1.y = 0.5f * y3 * (1.f + erff(y3 * 0.70710678118654752f));
            *(float2*)&orow[col] = o0;
            *(float2*)&orow8[col] = o1;
        }
    }
}

// ---------------------------------------------------------------------------
extern "C" void kernel_launch(void* const* d_in, const int* in_sizes, int n_in,
                              void* d_out, int out_size) {
    const float* x     = (const float*)d_in[0];
    const float* Wq    = (const float*)d_in[1];
    const float* Wk    = (const float*)d_in[2];
    const float* Wv    = (const float*)d_in[3];
    const float* Wo    = (const float*)d_in[4];
    const float* gamma = (const float*)d_in[5];
    const float* beta  = (const float*)d_in[6];
    float* out = (float*)d_out;

    cudaFuncSetAttribute(attn_kernel,
                         cudaFuncAttributeMaxDynamicSharedMemorySize, SMEM_BYTES);

    wvo_kernel<<<128, 128>>>(Wv, Wo);
    prep_kernel<<<3, 128>>>(Wq, Wk);
    attn_kernel<<<dim3(64, 8), 512, SMEM_BYTES>>>(x, gamma, beta, out);
}

// round 6
// speedup vs baseline: 1.1234x; 1.1234x over previous
#include <cuda_runtime.h>
#include <cuda_bf16.h>
#include <math.h>
#include <stdint.h>

#define PITCH 136                 // bf16 elements per smem row (272B)

// ---- smem layout (byte offsets) ----
#define XH_OFF  0
#define XL_OFF  34816
#define W2H_OFF 69632             // Wk, later Wvo
#define W2L_OFF 104448
#define W1H_OFF 139264            // Wq, later K
#define W1L_OFF 174080
#define GB_OFF  208896            // gamma, beta, gelu(beta): 3*128 floats
#define SMEM_BYTES (208896 + 1536)

// ---- global scratch ----
__device__ float g_Wvo[128 * 128];
__device__ __align__(16) unsigned short g_wh[3][128 * PITCH];  // [n][k] hi
__device__ __align__(16) unsigned short g_wl[3][128 * PITCH];  // [n][k] lo

// ---------------------------------------------------------------------------
static __device__ __forceinline__ uint32_t smem_u32(const void* p) {
    uint32_t a;
    asm("{ .reg .u64 t; cvta.to.shared.u64 t, %1; cvt.u32.u64 %0, t; }"
        : "=r"(a) : "l"(p));
    return a;
}
static __device__ __forceinline__ void cp16(uint32_t dst, const void* src) {
    asm volatile("cp.async.cg.shared.global [%0], [%1], 16;"
                 :: "r"(dst), "l"(src) : "memory");
}
#define CP_COMMIT() asm volatile("cp.async.commit_group;" ::: "memory")
#define CP_WAIT0()  asm volatile("cp.async.wait_group 0;" ::: "memory")

static __device__ __forceinline__ void split2(float a, float b,
                                              uint32_t& hi, uint32_t& lo) {
    __nv_bfloat16 ha = __float2bfloat16(a), hb = __float2bfloat16(b);
    float ra = a - __bfloat162float(ha);
    float rb = b - __bfloat162float(hb);
    __nv_bfloat16 la = __float2bfloat16(ra), lb = __float2bfloat16(rb);
    hi = ((uint32_t)__bfloat16_as_ushort(hb) << 16) | __bfloat16_as_ushort(ha);
    lo = ((uint32_t)__bfloat16_as_ushort(lb) << 16) | __bfloat16_as_ushort(la);
}
static __device__ __forceinline__ void mma_bf16(float c[4], uint32_t a0,
                                                uint32_t a1, uint32_t a2,
                                                uint32_t a3, uint32_t b0,
                                                uint32_t b1) {
    asm volatile(
        "mma.sync.aligned.m16n8k16.row.col.f32.bf16.bf16.f32 "
        "{%0,%1,%2,%3}, {%4,%5,%6,%7}, {%8,%9}, {%0,%1,%2,%3};"
        : "+f"(c[0]), "+f"(c[1]), "+f"(c[2]), "+f"(c[3])
        : "r"(a0), "r"(a1), "r"(a2), "r"(a3), "r"(b0), "r"(b1));
}
static __device__ __forceinline__ void ldsm4(uint32_t& r0, uint32_t& r1,
                                             uint32_t& r2, uint32_t& r3,
                                             uint32_t addr) {
    asm volatile("ldmatrix.sync.aligned.m8n8.x4.shared.b16 {%0,%1,%2,%3}, [%4];"
                 : "=r"(r0), "=r"(r1), "=r"(r2), "=r"(r3) : "r"(addr));
}
static __device__ __forceinline__ void ldsm4t(uint32_t& r0, uint32_t& r1,
                                              uint32_t& r2, uint32_t& r3,
                                              uint32_t addr) {
    asm volatile(
        "ldmatrix.sync.aligned.m8n8.x4.trans.shared.b16 {%0,%1,%2,%3}, [%4];"
        : "=r"(r0), "=r"(r1), "=r"(r2), "=r"(r3) : "r"(addr));
}

static __device__ __forceinline__ void zero_acc(float acc[16][4]) {
#pragma unroll
    for (int j = 0; j < 16; ++j)
#pragma unroll
        for (int i = 0; i < 4; ++i) acc[j][i] = 0.f;
}

// 12 MMAs over 4 independent acc chains (reuse distance 4) for two jp-pairs.
// 3-pass split: hi*bhi + hi*blo + lo*bhi.
static __device__ __forceinline__ void mma_oct(
    float a0[4], float a1[4], float a2[4], float a3[4], const uint32_t ah[4],
    const uint32_t al[4], const uint32_t bp[4], const uint32_t cp[4],
    const uint32_t bq[4], const uint32_t cq[4]) {
    mma_bf16(a0, ah[0], ah[1], ah[2], ah[3], bp[0], bp[1]);
    mma_bf16(a1, ah[0], ah[1], ah[2], ah[3], bp[2], bp[3]);
    mma_bf16(a2, ah[0], ah[1], ah[2], ah[3], bq[0], bq[1]);
    mma_bf16(a3, ah[0], ah[1], ah[2], ah[3], bq[2], bq[3]);
    mma_bf16(a0, ah[0], ah[1], ah[2], ah[3], cp[0], cp[1]);
    mma_bf16(a1, ah[0], ah[1], ah[2], ah[3], cp[2], cp[3]);
    mma_bf16(a2, ah[0], ah[1], ah[2], ah[3], cq[0], cq[1]);
    mma_bf16(a3, ah[0], ah[1], ah[2], ah[3], cq[2], cq[3]);
    mma_bf16(a0, al[0], al[1], al[2], al[3], bp[0], bp[1]);
    mma_bf16(a1, al[0], al[1], al[2], al[3], bp[2], bp[3]);
    mma_bf16(a2, al[0], al[1], al[2], al[3], bq[0], bq[1]);
    mma_bf16(a3, al[0], al[1], al[2], al[3], bq[2], bq[3]);
}

// acc = A(smem, ldmatrix) @ B(smem [n][k], ldmatrix)
static __device__ __forceinline__ void gemm_sAB(uint32_t aH, uint32_t aL,
                                                uint32_t bH, uint32_t bL,
                                                float acc[16][4]) {
    zero_acc(acc);
#pragma unroll
    for (int kk = 0; kk < 8; ++kk) {
        uint32_t ah[4], al[4];
        ldsm4(ah[0], ah[1], ah[2], ah[3], aH + kk * 32);
        ldsm4(al[0], al[1], al[2], al[3], aL + kk * 32);
#pragma unroll
        for (int jpp = 0; jpp < 4; ++jpp) {
            uint32_t op =
                (uint32_t)((2 * jpp) * 16 * PITCH + kk * 16) * 2;
            uint32_t oq =
                (uint32_t)((2 * jpp + 1) * 16 * PITCH + kk * 16) * 2;
            uint32_t bp[4], cp[4], bq[4], cq[4];
            ldsm4(bp[0], bp[1], bp[2], bp[3], bH + op);
            ldsm4(cp[0], cp[1], cp[2], cp[3], bL + op);
            ldsm4(bq[0], bq[1], bq[2], bq[3], bH + oq);
            ldsm4(cq[0], cq[1], cq[2], cq[3], bL + oq);
            mma_oct(acc[4 * jpp], acc[4 * jpp + 1], acc[4 * jpp + 2],
                    acc[4 * jpp + 3], ah, al, bp, cp, bq, cq);
        }
    }
}

// acc = A(register frags) @ B(smem [n][k], ldmatrix)
static __device__ __forceinline__ void gemm_rAB(const uint32_t* Ah,
                                                const uint32_t* Al,
                                                uint32_t bH, uint32_t bL,
                                                float acc[16][4]) {
    zero_acc(acc);
#pragma unroll
    for (int kk = 0; kk < 8; ++kk) {
#pragma unroll
        for (int jpp = 0; jpp < 4; ++jpp) {
            uint32_t op =
                (uint32_t)((2 * jpp) * 16 * PITCH + kk * 16) * 2;
            uint32_t oq =
                (uint32_t)((2 * jpp + 1) * 16 * PITCH + kk * 16) * 2;
            uint32_t bp[4], cp[4], bq[4], cq[4];
            ldsm4(bp[0], bp[1], bp[2], bp[3], bH + op);
            ldsm4(cp[0], cp[1], cp[2], cp[3], bL + op);
            ldsm4(bq[0], bq[1], bq[2], bq[3], bH + oq);
            ldsm4(cq[0], cq[1], cq[2], cq[3], bL + oq);
            mma_oct(acc[4 * jpp], acc[4 * jpp + 1], acc[4 * jpp + 2],
                    acc[4 * jpp + 3], &Ah[4 * kk], &Al[4 * kk], bp, cp, bq,
                    cq);
        }
    }
}

// acc = A(register frags) @ X (smem row-major [tok][d], ldmatrix.trans)
static __device__ __forceinline__ void gemm_rTX(const uint32_t* Ah,
                                                const uint32_t* Al,
                                                uint32_t xH, uint32_t xL,
                                                float acc[16][4]) {
    zero_acc(acc);
#pragma unroll
    for (int kk = 0; kk < 8; ++kk) {
#pragma unroll
        for (int jpp = 0; jpp < 4; ++jpp) {
            uint32_t op =
                (uint32_t)(kk * 16 * PITCH + (2 * jpp) * 16) * 2;
            uint32_t oq =
                (uint32_t)(kk * 16 * PITCH + (2 * jpp + 1) * 16) * 2;
            uint32_t bp[4], cp[4], bq[4], cq[4];
            ldsm4t(bp[0], bp[1], bp[2], bp[3], xH + op);
            ldsm4t(cp[0], cp[1], cp[2], cp[3], xL + op);
            ldsm4t(bq[0], bq[1], bq[2], bq[3], xH + oq);
            ldsm4t(cq[0], cq[1], cq[2], cq[3], xL + oq);
            mma_oct(acc[4 * jpp], acc[4 * jpp + 1], acc[4 * jpp + 2],
                    acc[4 * jpp + 3], &Ah[4 * kk], &Al[4 * kk], bp, cp, bq,
                    cq);
        }
    }
}

// C fragments -> A fragments (hi/lo) of next GEMM (pure register op)
static __device__ __forceinline__ void to_afrag(const float acc[16][4],
                                                uint32_t* Ah, uint32_t* Al) {
#pragma unroll
    for (int kk = 0; kk < 8; ++kk) {
        split2(acc[2 * kk][0], acc[2 * kk][1], Ah[4 * kk + 0], Al[4 * kk + 0]);
        split2(acc[2 * kk][2], acc[2 * kk][3], Ah[4 * kk + 1], Al[4 * kk + 1]);
        split2(acc[2 * kk + 1][0], acc[2 * kk + 1][1], Ah[4 * kk + 2],
               Al[4 * kk + 2]);
        split2(acc[2 * kk + 1][2], acc[2 * kk + 1][3], Ah[4 * kk + 3],
               Al[4 * kk + 3]);
    }
}

// ---------------------------------------------------------------------------
// Wvo = Wv @ Wo. grid 16, block 256, Wo staged in dynamic smem.
// ---------------------------------------------------------------------------
__global__ void wvo_kernel(const float* __restrict__ Wv,
                           const float* __restrict__ Wo) {
    extern __shared__ float ws[];
    float* swo = ws;              // 128*128
    float* swv = ws + 16384;      // 8*128
    const int tid = threadIdx.x;
    const int r0 = blockIdx.x * 8;
    {
        const float4* wo4 = (const float4*)Wo;
        float4* s4 = (float4*)swo;
        for (int i = tid; i < 4096; i += 256) s4[i] = wo4[i];
        const float4* wv4 = (const float4*)(Wv + r0 * 128);
        if (tid < 256) ((float4*)swv)[tid] = wv4[tid];
    }
    __syncthreads();
    const int lr = tid >> 5, c = (tid & 31) * 4;
    float4 a = make_float4(0.f, 0.f, 0.f, 0.f);
#pragma unroll 4
    for (int k = 0; k < 128; ++k) {
        float v = swv[lr * 128 + k];
        float4 b = *(const float4*)&swo[k * 128 + c];
        a.x = fmaf(v, b.x, a.x);
        a.y = fmaf(v, b.y, a.y);
        a.z = fmaf(v, b.z, a.z);
        a.w = fmaf(v, b.w, a.w);
    }
    *(float4*)&g_Wvo[(r0 + lr) * 128 + c] = a;
}

// Split weights -> transposed [n][k] pitched bf16 hi/lo (Wq pre-scaled)
__global__ void prep_kernel(const float* __restrict__ Wq,
                            const float* __restrict__ Wk) {
    int m = blockIdx.x, n = threadIdx.x;
    const float* src = (m == 0) ? Wq : (m == 1) ? Wk : g_Wvo;
    float scale = (m == 0) ? 0.08838834764831845f : 1.0f;
    int k0 = blockIdx.y * 8;
#pragma unroll
    for (int k = k0; k < k0 + 8; ++k) {
        float w = src[k * 128 + n] * scale;
        __nv_bfloat16 h = __float2bfloat16(w);
        float r = w - __bfloat162float(h);
        __nv_bfloat16 l = __float2bfloat16(r);
        g_wh[m][n * PITCH + k] = __bfloat16_as_ushort(h);
        g_wl[m][n * PITCH + k] = __bfloat16_as_ushort(l);
    }
}

// ---------------------------------------------------------------------------
// Main fused kernel: one CTA per 128-token block, 256 threads (8 warps).
// Warp w owns output rows [16w, 16w+16). Also writes the mirrored
// zeros-passer block (gelu(beta) broadcast).
// ---------------------------------------------------------------------------
__global__ void __launch_bounds__(256, 1) attn_kernel(
    const float* __restrict__ x, const float* __restrict__ gamma,
    const float* __restrict__ beta, float* __restrict__ out) {
    extern __shared__ char smc[];
    const int tid = threadIdx.x;
    const int lane = tid & 31;
    const int w = tid >> 5;
    const int g = lane >> 2, t = lane & 3;
    const int R = 16 * w;

    const uint32_t xh_u = smem_u32(smc + XH_OFF);
    const uint32_t xl_u = smem_u32(smc + XL_OFF);
    const uint32_t w1h_u = smem_u32(smc + W1H_OFF);
    const uint32_t w1l_u = smem_u32(smc + W1L_OFF);
    const uint32_t w2h_u = smem_u32(smc + W2H_OFF);
    const uint32_t w2l_u = smem_u32(smc + W2L_OFF);

    const int L = lane;
    const uint32_t offA =
        (uint32_t)(((L & 7) + (L & 8)) * PITCH + ((L & 16) ? 8 : 0)) * 2;
    const uint32_t offB =
        (uint32_t)(((L & 7) + ((L & 16) ? 8 : 0)) * PITCH + (L & 8)) * 2;
    const uint32_t offT =
        (uint32_t)((L & 15) * PITCH + ((L & 16) ? 8 : 0)) * 2;

    // --- async weight prefetch: Wq -> W1, Wk -> W2 ---
    for (int i = tid; i < 2176; i += 256) {
        cp16(w1h_u + i * 16, (const char*)g_wh[0] + i * 16);
        cp16(w1l_u + i * 16, (const char*)g_wl[0] + i * 16);
        cp16(w2h_u + i * 16, (const char*)g_wh[1] + i * 16);
        cp16(w2l_u + i * 16, (const char*)g_wl[1] + i * 16);
    }
    CP_COMMIT();

    float* sgam = (float*)(smc + GB_OFF);
    float* sbet = sgam + 128;
    float* sgel = sgam + 256;
    if (tid < 128) {
        float b = beta[tid];
        sgam[tid] = gamma[tid];
        sbet[tid] = b;
        sgel[tid] = 0.5f * b * (1.f + erff(b * 0.70710678118654752f));
    }

    // --- load X tile -> bf16 hi/lo pitched smem ---
    const int xrow = tid >> 1, xc0 = (tid & 1) * 64;
    {
        unsigned short* XH = (unsigned short*)(smc + XH_OFF);
        unsigned short* XL = (unsigned short*)(smc + XL_OFF);
        const long long base =
            ((long long)blockIdx.y * 8192 + (long long)blockIdx.x * 128) * 128;
        const float4* xg = (const float4*)(x + base + xrow * 128 + xc0);
#pragma unroll
        for (int i = 0; i < 16; ++i) {
            float4 f = xg[i];
            uint32_t h0, l0, h1, l1;
            split2(f.x, f.y, h0, l0);
            split2(f.z, f.w, h1, l1);
            *(uint32_t*)&XH[xrow * PITCH + xc0 + 4 * i] = h0;
            *(uint32_t*)&XH[xrow * PITCH + xc0 + 4 * i + 2] = h1;
            *(uint32_t*)&XL[xrow * PITCH + xc0 + 4 * i] = l0;
            *(uint32_t*)&XL[xrow * PITCH + xc0 + 4 * i + 2] = l1;
        }
    }
    CP_WAIT0();
    __syncthreads();

    // --- mirrored zeros-passer block: out2 = gelu(beta) broadcast ---
    {
        float* o2 = out + (long long)blockIdx.y * 16384 * 128 +
                    ((long long)8192 + blockIdx.x * 128 + xrow) * 128 + xc0;
#pragma unroll
        for (int i = 0; i < 16; ++i)
            *(float4*)(o2 + 4 * i) =
                make_float4(sgel[xc0 + 4 * i], sgel[xc0 + 4 * i + 1],
                            sgel[xc0 + 4 * i + 2], sgel[xc0 + 4 * i + 3]);
    }

    float acc[16][4];
    uint32_t Ah[32], Al[32];
    const uint32_t aH = xh_u + (uint32_t)(R * PITCH) * 2 + offA;
    const uint32_t aL = xl_u + (uint32_t)(R * PITCH) * 2 + offA;

    // ---- Q = X @ Wq' (scale folded) ----
    gemm_sAB(aH, aL, w1h_u + offB, w1l_u + offB, acc);
    to_afrag(acc, Ah, Al);  // Q frags

    // ---- K = X @ Wk ----
    gemm_sAB(aH, aL, w2h_u + offB, w2l_u + offB, acc);
    __syncthreads();  // all W1 (Wq) / W2 (Wk) reads done

    // store K -> W1 region (bf16 hi/lo, row-major [tok][d])
    {
        unsigned short* KH = (unsigned short*)(smc + W1H_OFF);
        unsigned short* KL = (unsigned short*)(smc + W1L_OFF);
#pragma unroll
        for (int j = 0; j < 16; ++j) {
            const int col = 8 * j + 2 * t;
            uint32_t h, l;
            split2(acc[j][0], acc[j][1], h, l);
            *(uint32_t*)&KH[(R + g) * PITCH + col] = h;
            *(uint32_t*)&KL[(R + g) * PITCH + col] = l;
            split2(acc[j][2], acc[j][3], h, l);
            *(uint32_t*)&KH[(R + g + 8) * PITCH + col] = h;
            *(uint32_t*)&KL[(R + g + 8) * PITCH + col] = l;
        }
    }
    // async prefetch Wvo -> W2 (hidden behind S + softmax + T)
    for (int i = tid; i < 2176; i += 256) {
        cp16(w2h_u + i * 16, (const char*)g_wh[2] + i * 16);
        cp16(w2l_u + i * 16, (const char*)g_wl[2] + i * 16);
    }
    CP_COMMIT();
    __syncthreads();  // K visible

    // ---- S = Q @ K^T ----
    gemm_rAB(Ah, Al, w1h_u + offB, w1l_u + offB, acc);

    // ---- softmax per row ----
    {
        float mx0 = -1e30f, mx1 = -1e30f;
#pragma unroll
        for (int j = 0; j < 16; ++j) {
            mx0 = fmaxf(mx0, fmaxf(acc[j][0], acc[j][1]));
            mx1 = fmaxf(mx1, fmaxf(acc[j][2], acc[j][3]));
        }
        mx0 = fmaxf(mx0, __shfl_xor_sync(0xffffffffu, mx0, 1));
        mx0 = fmaxf(mx0, __shfl_xor_sync(0xffffffffu, mx0, 2));
        mx1 = fmaxf(mx1, __shfl_xor_sync(0xffffffffu, mx1, 1));
        mx1 = fmaxf(mx1, __shfl_xor_sync(0xffffffffu, mx1, 2));
        float s0 = 0.f, s1 = 0.f;
#pragma unroll
        for (int j = 0; j < 16; ++j) {
            acc[j][0] = __expf(acc[j][0] - mx0);
            acc[j][1] = __expf(acc[j][1] - mx0);
            acc[j][2] = __expf(acc[j][2] - mx1);
            acc[j][3] = __expf(acc[j][3] - mx1);
            s0 += acc[j][0] + acc[j][1];
            s1 += acc[j][2] + acc[j][3];
        }
        s0 += __shfl_xor_sync(0xffffffffu, s0, 1);
        s0 += __shfl_xor_sync(0xffffffffu, s0, 2);
        s1 += __shfl_xor_sync(0xffffffffu, s1, 1);
        s1 += __shfl_xor_sync(0xffffffffu, s1, 2);
        float i0 = 1.0f / s0, i1 = 1.0f / s1;
#pragma unroll
        for (int j = 0; j < 16; ++j) {
            acc[j][0] *= i0;
            acc[j][1] *= i0;
            acc[j][2] *= i1;
            acc[j][3] *= i1;
        }
    }
    to_afrag(acc, Ah, Al);  // P frags

    // ---- T = P @ X (ldmatrix.trans on X) ----
    gemm_rTX(Ah, Al, xh_u + offT, xl_u + offT, acc);
    to_afrag(acc, Ah, Al);  // T frags

    CP_WAIT0();
    __syncthreads();  // Wvo visible in W2

    // ---- H = T @ Wvo ----
    gemm_rAB(Ah, Al, w2h_u + offB, w2l_u + offB, acc);

    // ---- LayerNorm + exact GELU + store ----
    {
        float s0 = 0.f, s1 = 0.f;
#pragma unroll
        for (int j = 0; j < 16; ++j) {
            s0 += acc[j][0] + acc[j][1];
            s1 += acc[j][2] + acc[j][3];
        }
        s0 += __shfl_xor_sync(0xffffffffu, s0, 1);
        s0 += __shfl_xor_sync(0xffffffffu, s0, 2);
        s1 += __shfl_xor_sync(0xffffffffu, s1, 1);
        s1 += __shfl_xor_sync(0xffffffffu, s1, 2);
        float mu0 = s0 * (1.0f / 128.0f), mu1 = s1 * (1.0f / 128.0f);
        float q0 = 0.f, q1 = 0.f;
#pragma unroll
        for (int j = 0; j < 16; ++j) {
            float d0 = acc[j][0] - mu0, d1 = acc[j][1] - mu0;
            float d2 = acc[j][2] - mu1, d3 = acc[j][3] - mu1;
            q0 += d0 * d0 + d1 * d1;
            q1 += d2 * d2 + d3 * d3;
        }
        q0 += __shfl_xor_sync(0xffffffffu, q0, 1);
        q0 += __shfl_xor_sync(0xffffffffu, q0, 2);
        q1 += __shfl_xor_sync(0xffffffffu, q1, 1);
        q1 += __shfl_xor_sync(0xffffffffu, q1, 2);
        float r0 = rsqrtf(q0 * (1.0f / 128.0f) + 1e-5f);
        float r1 = rsqrtf(q1 * (1.0f / 128.0f) + 1e-5f);

        float* orow = out + ((long long)blockIdx.y * 16384 +
                             (long long)blockIdx.x * 128 + R + g) * 128;
        float* orow8 = orow + 8 * 128;
#pragma unroll
        for (int j = 0; j < 16; ++j) {
            const int col = 8 * j + 2 * t;
            float ga0 = sgam[col], ga1 = sgam[col + 1];
            float be0 = sbet[col], be1 = sbet[col + 1];
            float y0 = (acc[j][0] - mu0) * r0 * ga0 + be0;
            float y1 = (acc[j][1] - mu0) * r0 * ga1 + be1;
            float y2 = (acc[j][2] - mu1) * r1 * ga0 + be0;
            float y3 = (acc[j][3] - mu1) * r1 * ga1 + be1;
            float2 o0, o1;
            o0.x = 0.5f * y0 * (1.f + erff(y0 * 0.70710678118654752f));
            o0.y = 0.5f * y1 * (1.f + erff(y1 * 0.70710678118654752f));
            o1.x = 0.5f * y2 * (1.f + erff(y2 * 0.70710678118654752f));
            o1.y = 0.5f * y3 * (1.f + erff(y3 * 0.70710678118654752f));
            *(float2*)&orow[col] = o0;
            *(float2*)&orow8[col] = o1;
        }
    }
}

// ---------------------------------------------------------------------------
extern "C" void kernel_launch(void* const* d_in, const int* in_sizes, int n_in,
                              void* d_out, int out_size) {
    const float* x     = (const float*)d_in[0];
    const float* Wq    = (const float*)d_in[1];
    const float* Wk    = (const float*)d_in[2];
    const float* Wv    = (const float*)d_in[3];
    const float* Wo    = (const float*)d_in[4];
    const float* gamma = (const float*)d_in[5];
    const float* beta  = (const float*)d_in[6];
    float* out = (float*)d_out;

    cudaFuncSetAttribute(attn_kernel,
                         cudaFuncAttributeMaxDynamicSharedMemorySize, SMEM_BYTES);
    cudaFuncSetAttribute(wvo_kernel,
                         cudaFuncAttributeMaxDynamicSharedMemorySize, 69632);

    wvo_kernel<<<16, 256, 69632>>>(Wv, Wo);
    prep_kernel<<<dim3(3, 16), 128>>>(Wq, Wk);
    attn_kernel<<<dim3(64, 8), 256, SMEM_BYTES>>>(x, gamma, beta, out);
}

// round 7
// speedup vs baseline: 1.3073x; 1.1637x over previous
#include <cuda_runtime.h>
#include <cuda_bf16.h>
#include <math.h>
#include <stdint.h>

#define PITCH 136                 // bf16 elements per smem row (272B)

// ---- attn smem layout (byte offsets) ----
#define XH_OFF  0                 // X hi (never overwritten)
#define XL_OFF  34816             // X lo
#define W1H_OFF 69632             // M hi  -> V hi
#define W1L_OFF 104448            // M lo  -> V lo
#define W2H_OFF 139264            // Wvo hi
#define W2L_OFF 174080            // Wvo lo
#define GB_OFF  208896            // gamma, beta, gelu(beta): 3*128 floats
#define SMEM_BYTES (208896 + 1536)

// prep smem: A staged 128x129 f32 + B rows 8x128 f32
#define PREP_SMEM (128 * 129 * 4 + 8 * 128 * 4)

// ---- global scratch: [0] = M = Wq Wk^T / sqrt(d), [1] = Wvo = Wv Wo ----
// stored transposed as B[n][k], pitched, bf16 hi/lo
__device__ __align__(16) unsigned short g_wh[2][128 * PITCH];
__device__ __align__(16) unsigned short g_wl[2][128 * PITCH];

// ---------------------------------------------------------------------------
static __device__ __forceinline__ uint32_t smem_u32(const void* p) {
    uint32_t a;
    asm("{ .reg .u64 t; cvta.to.shared.u64 t, %1; cvt.u32.u64 %0, t; }"
        : "=r"(a) : "l"(p));
    return a;
}
static __device__ __forceinline__ void cp16(uint32_t dst, const void* src) {
    asm volatile("cp.async.cg.shared.global [%0], [%1], 16;"
                 :: "r"(dst), "l"(src) : "memory");
}
#define CP_COMMIT() asm volatile("cp.async.commit_group;" ::: "memory")
#define CP_WAIT0()  asm volatile("cp.async.wait_group 0;" ::: "memory")

static __device__ __forceinline__ void split2(float a, float b,
                                              uint32_t& hi, uint32_t& lo) {
    __nv_bfloat16 ha = __float2bfloat16(a), hb = __float2bfloat16(b);
    float ra = a - __bfloat162float(ha);
    float rb = b - __bfloat162float(hb);
    __nv_bfloat16 la = __float2bfloat16(ra), lb = __float2bfloat16(rb);
    hi = ((uint32_t)__bfloat16_as_ushort(hb) << 16) | __bfloat16_as_ushort(ha);
    lo = ((uint32_t)__bfloat16_as_ushort(lb) << 16) | __bfloat16_as_ushort(la);
}
static __device__ __forceinline__ void mma_bf16(float c[4], uint32_t a0,
                                                uint32_t a1, uint32_t a2,
                                                uint32_t a3, uint32_t b0,
                                                uint32_t b1) {
    asm volatile(
        "mma.sync.aligned.m16n8k16.row.col.f32.bf16.bf16.f32 "
        "{%0,%1,%2,%3}, {%4,%5,%6,%7}, {%8,%9}, {%0,%1,%2,%3};"
        : "+f"(c[0]), "+f"(c[1]), "+f"(c[2]), "+f"(c[3])
        : "r"(a0), "r"(a1), "r"(a2), "r"(a3), "r"(b0), "r"(b1));
}
static __device__ __forceinline__ void ldsm4(uint32_t& r0, uint32_t& r1,
                                             uint32_t& r2, uint32_t& r3,
                                             uint32_t addr) {
    asm volatile("ldmatrix.sync.aligned.m8n8.x4.shared.b16 {%0,%1,%2,%3}, [%4];"
                 : "=r"(r0), "=r"(r1), "=r"(r2), "=r"(r3) : "r"(addr));
}
static __device__ __forceinline__ void ldsm4t(uint32_t& r0, uint32_t& r1,
                                              uint32_t& r2, uint32_t& r3,
                                              uint32_t addr) {
    asm volatile(
        "ldmatrix.sync.aligned.m8n8.x4.trans.shared.b16 {%0,%1,%2,%3}, [%4];"
        : "=r"(r0), "=r"(r1), "=r"(r2), "=r"(r3) : "r"(addr));
}

static __device__ __forceinline__ void zero_acc(float acc[16][4]) {
#pragma unroll
    for (int j = 0; j < 16; ++j)
#pragma unroll
        for (int i = 0; i < 4; ++i) acc[j][i] = 0.f;
}

// 12 MMAs over 4 independent acc chains for two jp-pairs (3-pass split)
static __device__ __forceinline__ void mma_oct(
    float a0[4], float a1[4], float a2[4], float a3[4], const uint32_t ah[4],
    const uint32_t al[4], const uint32_t bp[4], const uint32_t cp[4],
    const uint32_t bq[4], const uint32_t cq[4]) {
    mma_bf16(a0, ah[0], ah[1], ah[2], ah[3], bp[0], bp[1]);
    mma_bf16(a1, ah[0], ah[1], ah[2], ah[3], bp[2], bp[3]);
    mma_bf16(a2, ah[0], ah[1], ah[2], ah[3], bq[0], bq[1]);
    mma_bf16(a3, ah[0], ah[1], ah[2], ah[3], bq[2], bq[3]);
    mma_bf16(a0, ah[0], ah[1], ah[2], ah[3], cp[0], cp[1]);
    mma_bf16(a1, ah[0], ah[1], ah[2], ah[3], cp[2], cp[3]);
    mma_bf16(a2, ah[0], ah[1], ah[2], ah[3], cq[0], cq[1]);
    mma_bf16(a3, ah[0], ah[1], ah[2], ah[3], cq[2], cq[3]);
    mma_bf16(a0, al[0], al[1], al[2], al[3], bp[0], bp[1]);
    mma_bf16(a1, al[0], al[1], al[2], al[3], bp[2], bp[3]);
    mma_bf16(a2, al[0], al[1], al[2], al[3], bq[0], bq[1]);
    mma_bf16(a3, al[0], al[1], al[2], al[3], bq[2], bq[3]);
}

// acc = A(smem rows, ldmatrix) @ B(smem [n][k], ldmatrix)
static __device__ __forceinline__ void gemm_sAB(uint32_t aH, uint32_t aL,
                                                uint32_t bH, uint32_t bL,
                                                float acc[16][4]) {
    zero_acc(acc);
#pragma unroll
    for (int kk = 0; kk < 8; ++kk) {
        uint32_t ah[4], al[4];
        ldsm4(ah[0], ah[1], ah[2], ah[3], aH + kk * 32);
        ldsm4(al[0], al[1], al[2], al[3], aL + kk * 32);
#pragma unroll
        for (int jpp = 0; jpp < 4; ++jpp) {
            uint32_t op = (uint32_t)((2 * jpp) * 16 * PITCH + kk * 16) * 2;
            uint32_t oq = (uint32_t)((2 * jpp + 1) * 16 * PITCH + kk * 16) * 2;
            uint32_t bp[4], cp[4], bq[4], cq[4];
            ldsm4(bp[0], bp[1], bp[2], bp[3], bH + op);
            ldsm4(cp[0], cp[1], cp[2], cp[3], bL + op);
            ldsm4(bq[0], bq[1], bq[2], bq[3], bH + oq);
            ldsm4(cq[0], cq[1], cq[2], cq[3], bL + oq);
            mma_oct(acc[4 * jpp], acc[4 * jpp + 1], acc[4 * jpp + 2],
                    acc[4 * jpp + 3], ah, al, bp, cp, bq, cq);
        }
    }
}

// acc = A(register frags) @ B(smem [n][k], ldmatrix)
static __device__ __forceinline__ void gemm_rAB(const uint32_t* Ah,
                                                const uint32_t* Al,
                                                uint32_t bH, uint32_t bL,
                                                float acc[16][4]) {
    zero_acc(acc);
#pragma unroll
    for (int kk = 0; kk < 8; ++kk) {
#pragma unroll
        for (int jpp = 0; jpp < 4; ++jpp) {
            uint32_t op = (uint32_t)((2 * jpp) * 16 * PITCH + kk * 16) * 2;
            uint32_t oq = (uint32_t)((2 * jpp + 1) * 16 * PITCH + kk * 16) * 2;
            uint32_t bp[4], cp[4], bq[4], cq[4];
            ldsm4(bp[0], bp[1], bp[2], bp[3], bH + op);
            ldsm4(cp[0], cp[1], cp[2], cp[3], bL + op);
            ldsm4(bq[0], bq[1], bq[2], bq[3], bH + oq);
            ldsm4(cq[0], cq[1], cq[2], cq[3], bL + oq);
            mma_oct(acc[4 * jpp], acc[4 * jpp + 1], acc[4 * jpp + 2],
                    acc[4 * jpp + 3], &Ah[4 * kk], &Al[4 * kk], bp, cp, bq,
                    cq);
        }
    }
}

// acc = A(register frags) @ B^T where B rows in smem (ldmatrix.trans)
static __device__ __forceinline__ void gemm_rTX(const uint32_t* Ah,
                                                const uint32_t* Al,
                                                uint32_t xH, uint32_t xL,
                                                float acc[16][4]) {
    zero_acc(acc);
#pragma unroll
    for (int kk = 0; kk < 8; ++kk) {
#pragma unroll
        for (int jpp = 0; jpp < 4; ++jpp) {
            uint32_t op = (uint32_t)(kk * 16 * PITCH + (2 * jpp) * 16) * 2;
            uint32_t oq = (uint32_t)(kk * 16 * PITCH + (2 * jpp + 1) * 16) * 2;
            uint32_t bp[4], cp[4], bq[4], cq[4];
            ldsm4t(bp[0], bp[1], bp[2], bp[3], xH + op);
            ldsm4t(cp[0], cp[1], cp[2], cp[3], xL + op);
            ldsm4t(bq[0], bq[1], bq[2], bq[3], xH + oq);
            ldsm4t(cq[0], cq[1], cq[2], cq[3], xL + oq);
            mma_oct(acc[4 * jpp], acc[4 * jpp + 1], acc[4 * jpp + 2],
                    acc[4 * jpp + 3], &Ah[4 * kk], &Al[4 * kk], bp, cp, bq,
                    cq);
        }
    }
}

// C fragments -> A fragments (hi/lo) of next GEMM
static __device__ __forceinline__ void to_afrag(const float acc[16][4],
                                                uint32_t* Ah, uint32_t* Al) {
#pragma unroll
    for (int kk = 0; kk < 8; ++kk) {
        split2(acc[2 * kk][0], acc[2 * kk][1], Ah[4 * kk + 0], Al[4 * kk + 0]);
        split2(acc[2 * kk][2], acc[2 * kk][3], Ah[4 * kk + 1], Al[4 * kk + 1]);
        split2(acc[2 * kk + 1][0], acc[2 * kk + 1][1], Ah[4 * kk + 2],
               Al[4 * kk + 2]);
        split2(acc[2 * kk + 1][2], acc[2 * kk + 1][3], Ah[4 * kk + 3],
               Al[4 * kk + 3]);
    }
}

// ---------------------------------------------------------------------------
// prep: grid (2, 16), block 256, dynamic smem.
//  m=0: B[n][k] = (Wq Wk^T)[k][n] / sqrt(d) = (Wq[k,:] . Wk[n,:]) * scale
//  m=1: B[n][k] = (Wv Wo)[k][n]            =  Wv[k,:] . Wo[:,n]
// split to bf16 hi/lo, store pitched.
// ---------------------------------------------------------------------------
__global__ void prep_kernel(const float* __restrict__ Wq,
                            const float* __restrict__ Wk,
                            const float* __restrict__ Wv,
                            const float* __restrict__ Wo) {
    extern __shared__ float ps[];
    float* As = ps;                // 128 x 129 (padded)
    float* Bs = ps + 128 * 129;    // 8 x 128
    const int m = blockIdx.x;
    const int n0 = blockIdx.y * 8;
    const int tid = threadIdx.x;

    const float* A = (m == 0) ? Wq : Wv;
    for (int idx = tid; idx < 16384; idx += 256) {
        int r = idx >> 7, c = idx & 127;
        As[r * 129 + c] = A[idx];
    }
    if (m == 0) {
        for (int idx = tid; idx < 1024; idx += 256)
            Bs[idx] = Wk[n0 * 128 + idx];
    } else {
        for (int idx = tid; idx < 1024; idx += 256) {
            int j = idx >> 7, i = idx & 127;
            Bs[j * 128 + i] = Wo[i * 128 + n0 + j];
        }
    }
    __syncthreads();

    const int k = tid & 127;
    const int jb = tid >> 7;
    const float scale = (m == 0) ? 0.08838834764831845f : 1.0f;
#pragma unroll
    for (int jj = 0; jj < 4; ++jj) {
        int j = jb + 2 * jj;
        float acc = 0.f;
#pragma unroll 8
        for (int i = 0; i < 128; ++i)
            acc = fmaf(As[k * 129 + i], Bs[j * 128 + i], acc);
        acc *= scale;
        __nv_bfloat16 h = __float2bfloat16(acc);
        float r = acc - __bfloat162float(h);
        __nv_bfloat16 l = __float2bfloat16(r);
        int n = n0 + j;
        g_wh[m][n * PITCH + k] = __bfloat16_as_ushort(h);
        g_wl[m][n * PITCH + k] = __bfloat16_as_ushort(l);
    }
}

// ---------------------------------------------------------------------------
// Main fused kernel: one CTA per 128-token block, 256 threads (8 warps).
// Warp w owns output rows [16w, 16w+16). Also writes the mirrored
// zeros-passer block (gelu(beta) broadcast).
//   Q2 = X @ M;  S = Q2 @ X^T;  P = softmax(S);  V = X @ Wvo;  H = P @ V
// ---------------------------------------------------------------------------
__global__ void __launch_bounds__(256, 1) attn_kernel(
    const float* __restrict__ x, const float* __restrict__ gamma,
    const float* __restrict__ beta, float* __restrict__ out) {
    extern __shared__ char smc[];
    const int tid = threadIdx.x;
    const int lane = tid & 31;
    const int w = tid >> 5;
    const int g = lane >> 2, t = lane & 3;
    const int R = 16 * w;

    const uint32_t xh_u = smem_u32(smc + XH_OFF);
    const uint32_t xl_u = smem_u32(smc + XL_OFF);
    const uint32_t w1h_u = smem_u32(smc + W1H_OFF);
    const uint32_t w1l_u = smem_u32(smc + W1L_OFF);
    const uint32_t w2h_u = smem_u32(smc + W2H_OFF);
    const uint32_t w2l_u = smem_u32(smc + W2L_OFF);

    const int L = lane;
    const uint32_t offA =
        (uint32_t)(((L & 7) + (L & 8)) * PITCH + ((L & 16) ? 8 : 0)) * 2;
    const uint32_t offB =
        (uint32_t)(((L & 7) + ((L & 16) ? 8 : 0)) * PITCH + (L & 8)) * 2;
    const uint32_t offT =
        (uint32_t)((L & 15) * PITCH + ((L & 16) ? 8 : 0)) * 2;

    // --- async prefetch: M -> W1, Wvo -> W2 (both up front) ---
    for (int i = tid; i < 2176; i += 256) {
        cp16(w1h_u + i * 16, (const char*)g_wh[0] + i * 16);
        cp16(w1l_u + i * 16, (const char*)g_wl[0] + i * 16);
        cp16(w2h_u + i * 16, (const char*)g_wh[1] + i * 16);
        cp16(w2l_u + i * 16, (const char*)g_wl[1] + i * 16);
    }
    CP_COMMIT();

    float* sgam = (float*)(smc + GB_OFF);
    float* sbet = sgam + 128;
    float* sgel = sgam + 256;
    if (tid < 128) {
        float b = beta[tid];
        sgam[tid] = gamma[tid];
        sbet[tid] = b;
        sgel[tid] = 0.5f * b * (1.f + erff(b * 0.70710678118654752f));
    }

    // --- load X tile -> bf16 hi/lo pitched smem ---
    const int xrow = tid >> 1, xc0 = (tid & 1) * 64;
    {
        unsigned short* XH = (unsigned short*)(smc + XH_OFF);
        unsigned short* XL = (unsigned short*)(smc + XL_OFF);
        const long long base =
            ((long long)blockIdx.y * 8192 + (long long)blockIdx.x * 128) * 128;
        const float4* xg = (const float4*)(x + base + xrow * 128 + xc0);
#pragma unroll
        for (int i = 0; i < 16; ++i) {
            float4 f = xg[i];
            uint32_t h0, l0, h1, l1;
            split2(f.x, f.y, h0, l0);
            split2(f.z, f.w, h1, l1);
            *(uint32_t*)&XH[xrow * PITCH + xc0 + 4 * i] = h0;
            *(uint32_t*)&XH[xrow * PITCH + xc0 + 4 * i + 2] = h1;
            *(uint32_t*)&XL[xrow * PITCH + xc0 + 4 * i] = l0;
            *(uint32_t*)&XL[xrow * PITCH + xc0 + 4 * i + 2] = l1;
        }
    }
    CP_WAIT0();
    __syncthreads();  // X + M + Wvo ready

    // --- mirrored zeros-passer block: out2 = gelu(beta) broadcast ---
    {
        float* o2 = out + (long long)blockIdx.y * 16384 * 128 +
                    ((long long)8192 + blockIdx.x * 128 + xrow) * 128 + xc0;
#pragma unroll
        for (int i = 0; i < 16; ++i)
            *(float4*)(o2 + 4 * i) =
                make_float4(sgel[xc0 + 4 * i], sgel[xc0 + 4 * i + 1],
                            sgel[xc0 + 4 * i + 2], sgel[xc0 + 4 * i + 3]);
    }

    float acc[16][4];
    uint32_t Ah[32], Al[32];
    const uint32_t aH = xh_u + (uint32_t)(R * PITCH) * 2 + offA;
    const uint32_t aL = xl_u + (uint32_t)(R * PITCH) * 2 + offA;

    // ---- Q2 = X @ M ----
    gemm_sAB(aH, aL, w1h_u + offB, w1l_u + offB, acc);
    to_afrag(acc, Ah, Al);  // Q2 frags

    // ---- S = Q2 @ X^T (B = X rows, non-trans ldmatrix) ----
    gemm_rAB(Ah, Al, xh_u + offB, xl_u + offB, acc);

    // ---- softmax per row ----
    {
        float mx0 = -1e30f, mx1 = -1e30f;
#pragma unroll
        for (int j = 0; j < 16; ++j) {
            mx0 = fmaxf(mx0, fmaxf(acc[j][0], acc[j][1]));
            mx1 = fmaxf(mx1, fmaxf(acc[j][2], acc[j][3]));
        }
        mx0 = fmaxf(mx0, __shfl_xor_sync(0xffffffffu, mx0, 1));
        mx0 = fmaxf(mx0, __shfl_xor_sync(0xffffffffu, mx0, 2));
        mx1 = fmaxf(mx1, __shfl_xor_sync(0xffffffffu, mx1, 1));
        mx1 = fmaxf(mx1, __shfl_xor_sync(0xffffffffu, mx1, 2));
        float s0 = 0.f, s1 = 0.f;
#pragma unroll
        for (int j = 0; j < 16; ++j) {
            acc[j][0] = __expf(acc[j][0] - mx0);
            acc[j][1] = __expf(acc[j][1] - mx0);
            acc[j][2] = __expf(acc[j][2] - mx1);
            acc[j][3] = __expf(acc[j][3] - mx1);
            s0 += acc[j][0] + acc[j][1];
            s1 += acc[j][2] + acc[j][3];
        }
        s0 += __shfl_xor_sync(0xffffffffu, s0, 1);
        s0 += __shfl_xor_sync(0xffffffffu, s0, 2);
        s1 += __shfl_xor_sync(0xffffffffu, s1, 1);
        s1 += __shfl_xor_sync(0xffffffffu, s1, 2);
        float i0 = 1.0f / s0, i1 = 1.0f / s1;
#pragma unroll
        for (int j = 0; j < 16; ++j) {
            acc[j][0] *= i0;
            acc[j][1] *= i0;
            acc[j][2] *= i1;
            acc[j][3] *= i1;
        }
    }
    to_afrag(acc, Ah, Al);  // P frags

    __syncthreads();  // all warps past Q2 -> W1 (M) region is recyclable

    // ---- V = X @ Wvo ----
    gemm_sAB(aH, aL, w2h_u + offB, w2l_u + offB, acc);

    // store V -> W1 region (bf16 hi/lo, row-major [tok][d])
    {
        unsigned short* VH = (unsigned short*)(smc + W1H_OFF);
        unsigned short* VL = (unsigned short*)(smc + W1L_OFF);
#pragma unroll
        for (int j = 0; j < 16; ++j) {
            const int col = 8 * j + 2 * t;
            uint32_t h, l;
            split2(acc[j][0], acc[j][1], h, l);
            *(uint32_t*)&VH[(R + g) * PITCH + col] = h;
            *(uint32_t*)&VL[(R + g) * PITCH + col] = l;
            split2(acc[j][2], acc[j][3], h, l);
            *(uint32_t*)&VH[(R + g + 8) * PITCH + col] = h;
            *(uint32_t*)&VL[(R + g + 8) * PITCH + col] = l;
        }
    }
    __syncthreads();  // V visible

    // ---- H = P @ V (ldmatrix.trans on V rows) ----
    gemm_rTX(Ah, Al, w1h_u + offT, w1l_u + offT, acc);

    // ---- LayerNorm + exact GELU + store ----
    {
        float s0 = 0.f, s1 = 0.f;
#pragma unroll
        for (int j = 0; j < 16; ++j) {
            s0 += acc[j][0] + acc[j][1];
            s1 += acc[j][2] + acc[j][3];
        }
        s0 += __shfl_xor_sync(0xffffffffu, s0, 1);
        s0 += __shfl_xor_sync(0xffffffffu, s0, 2);
        s1 += __shfl_xor_sync(0xffffffffu, s1, 1);
        s1 += __shfl_xor_sync(0xffffffffu, s1, 2);
        float mu0 = s0 * (1.0f / 128.0f), mu1 = s1 * (1.0f / 128.0f);
        float q0 = 0.f, q1 = 0.f;
#pragma unroll
        for (int j = 0; j < 16; ++j) {
            float d0 = acc[j][0] - mu0, d1 = acc[j][1] - mu0;
            float d2 = acc[j][2] - mu1, d3 = acc[j][3] - mu1;
            q0 += d0 * d0 + d1 * d1;
            q1 += d2 * d2 + d3 * d3;
        }
        q0 += __shfl_xor_sync(0xffffffffu, q0, 1);
        q0 += __shfl_xor_sync(0xffffffffu, q0, 2);
        q1 += __shfl_xor_sync(0xffffffffu, q1, 1);
        q1 += __shfl_xor_sync(0xffffffffu, q1, 2);
        float r0 = rsqrtf(q0 * (1.0f / 128.0f) + 1e-5f);
        float r1 = rsqrtf(q1 * (1.0f / 128.0f) + 1e-5f);

        float* orow = out + ((long long)blockIdx.y * 16384 +
                             (long long)blockIdx.x * 128 + R + g) * 128;
        float* orow8 = orow + 8 * 128;
#pragma unroll
        for (int j = 0; j < 16; ++j) {
            const int col = 8 * j + 2 * t;
            float ga0 = sgam[col], ga1 = sgam[col + 1];
            float be0 = sbet[col], be1 = sbet[col + 1];
            float y0 = (acc[j][0] - mu0) * r0 * ga0 + be0;
            float y1 = (acc[j][1] - mu0) * r0 * ga1 + be1;
            float y2 = (acc[j][2] - mu1) * r1 * ga0 + be0;
            float y3 = (acc[j][3] - mu1) * r1 * ga1 + be1;
            float2 o0, o1;
            o0.x = 0.5f * y0 * (1.f + erff(y0 * 0.70710678118654752f));
            o0.y = 0.5f * y1 * (1.f + erff(y1 * 0.70710678118654752f));
            o1.x = 0.5f * y2 * (1.f + erff(y2 * 0.70710678118654752f));
            o1.y = 0.5f * y3 * (1.f + erff(y3 * 0.70710678118654752f));
            *(float2*)&orow[col] = o0;
            *(float2*)&orow8[col] = o1;
        }
    }
}

// ---------------------------------------------------------------------------
extern "C" void kernel_launch(void* const* d_in, const int* in_sizes, int n_in,
                              void* d_out, int out_size) {
    const float* x     = (const float*)d_in[0];
    const float* Wq    = (const float*)d_in[1];
    const float* Wk    = (const float*)d_in[2];
    const float* Wv    = (const float*)d_in[3];
    const float* Wo    = (const float*)d_in[4];
    const float* gamma = (const float*)d_in[5];
    const float* beta  = (const float*)d_in[6];
    float* out = (float*)d_out;

    cudaFuncSetAttribute(attn_kernel,
                         cudaFuncAttributeMaxDynamicSharedMemorySize, SMEM_BYTES);
    cudaFuncSetAttribute(prep_kernel,
                         cudaFuncAttributeMaxDynamicSharedMemorySize, PREP_SMEM);

    prep_kernel<<<dim3(2, 16), 256, PREP_SMEM>>>(Wq, Wk, Wv, Wo);
    attn_kernel<<<dim3(64, 8), 256, SMEM_BYTES>>>(x, gamma, beta, out);
}

// round 8
// speedup vs baseline: 1.3433x; 1.0275x over previous
#include <cuda_runtime.h>
#include <cuda_bf16.h>
#include <math.h>
#include <stdint.h>

#define PITCH 136                 // bf16 elements per smem row (272B)

// ---- attn smem layout (byte offsets) ----
#define XH_OFF  0                 // X hi (never overwritten)
#define XL_OFF  34816             // X lo
#define W1H_OFF 69632             // M hi  -> V hi
#define W1L_OFF 104448            // M lo  -> V lo
#define W2H_OFF 139264            // Wvo hi
#define W2L_OFF 174080            // Wvo lo
#define GB_OFF  208896            // gamma, beta, gelu(beta): 3*128 floats
#define SMEM_BYTES (208896 + 1536)

// prep smem: A staged 128x129 f32 + B rows 8x128 f32
#define PREP_SMEM (128 * 129 * 4 + 8 * 128 * 4)

// ---- global scratch: [0] = M = Wq Wk^T / sqrt(d), [1] = Wvo = Wv Wo ----
__device__ __align__(16) unsigned short g_wh[2][128 * PITCH];
__device__ __align__(16) unsigned short g_wl[2][128 * PITCH];

// ---------------------------------------------------------------------------
static __device__ __forceinline__ uint32_t smem_u32(const void* p) {
    uint32_t a;
    asm("{ .reg .u64 t; cvta.to.shared.u64 t, %1; cvt.u32.u64 %0, t; }"
        : "=r"(a) : "l"(p));
    return a;
}
static __device__ __forceinline__ void cp16(uint32_t dst, const void* src) {
    asm volatile("cp.async.cg.shared.global [%0], [%1], 16;"
                 :: "r"(dst), "l"(src) : "memory");
}
#define CP_COMMIT() asm volatile("cp.async.commit_group;" ::: "memory")
#define CP_WAIT0()  asm volatile("cp.async.wait_group 0;" ::: "memory")

// packed hi/lo bf16 split: hi = bf16x2(a,b), lo = bf16x2 of residuals
static __device__ __forceinline__ void split2(float a, float b,
                                              uint32_t& hi, uint32_t& lo) {
    uint32_t h;
    asm("cvt.rn.bf16x2.f32 %0, %1, %2;" : "=r"(h) : "f"(b), "f"(a));
    float fa = __uint_as_float(h << 16);
    float fb = __uint_as_float(h & 0xffff0000u);
    uint32_t l;
    asm("cvt.rn.bf16x2.f32 %0, %1, %2;" : "=r"(l) : "f"(b - fb), "f"(a - fa));
    hi = h;
    lo = l;
}
static __device__ __forceinline__ void mma_bf16(float c[4], uint32_t a0,
                                                uint32_t a1, uint32_t a2,
                                                uint32_t a3, uint32_t b0,
                                                uint32_t b1) {
    asm volatile(
        "mma.sync.aligned.m16n8k16.row.col.f32.bf16.bf16.f32 "
        "{%0,%1,%2,%3}, {%4,%5,%6,%7}, {%8,%9}, {%0,%1,%2,%3};"
        : "+f"(c[0]), "+f"(c[1]), "+f"(c[2]), "+f"(c[3])
        : "r"(a0), "r"(a1), "r"(a2), "r"(a3), "r"(b0), "r"(b1));
}
static __device__ __forceinline__ void ldsm4(uint32_t& r0, uint32_t& r1,
                                             uint32_t& r2, uint32_t& r3,
                                             uint32_t addr) {
    asm volatile("ldmatrix.sync.aligned.m8n8.x4.shared.b16 {%0,%1,%2,%3}, [%4];"
                 : "=r"(r0), "=r"(r1), "=r"(r2), "=r"(r3) : "r"(addr));
}
static __device__ __forceinline__ void ldsm4t(uint32_t& r0, uint32_t& r1,
                                              uint32_t& r2, uint32_t& r3,
                                              uint32_t addr) {
    asm volatile(
        "ldmatrix.sync.aligned.m8n8.x4.trans.shared.b16 {%0,%1,%2,%3}, [%4];"
        : "=r"(r0), "=r"(r1), "=r"(r2), "=r"(r3) : "r"(addr));
}

static __device__ __forceinline__ void zero_acc(float acc[16][4]) {
#pragma unroll
    for (int j = 0; j < 16; ++j)
#pragma unroll
        for (int i = 0; i < 4; ++i) acc[j][i] = 0.f;
}

// 12 MMAs over 4 independent acc chains for two jp-pairs (3-pass split)
static __device__ __forceinline__ void mma_oct(
    float a0[4], float a1[4], float a2[4], float a3[4], const uint32_t ah[4],
    const uint32_t al[4], const uint32_t bp[4], const uint32_t cp[4],
    const uint32_t bq[4], const uint32_t cq[4]) {
    mma_bf16(a0, ah[0], ah[1], ah[2], ah[3], bp[0], bp[1]);
    mma_bf16(a1, ah[0], ah[1], ah[2], ah[3], bp[2], bp[3]);
    mma_bf16(a2, ah[0], ah[1], ah[2], ah[3], bq[0], bq[1]);
    mma_bf16(a3, ah[0], ah[1], ah[2], ah[3], bq[2], bq[3]);
    mma_bf16(a0, ah[0], ah[1], ah[2], ah[3], cp[0], cp[1]);
    mma_bf16(a1, ah[0], ah[1], ah[2], ah[3], cp[2], cp[3]);
    mma_bf16(a2, ah[0], ah[1], ah[2], ah[3], cq[0], cq[1]);
    mma_bf16(a3, ah[0], ah[1], ah[2], ah[3], cq[2], cq[3]);
    mma_bf16(a0, al[0], al[1], al[2], al[3], bp[0], bp[1]);
    mma_bf16(a1, al[0], al[1], al[2], al[3], bp[2], bp[3]);
    mma_bf16(a2, al[0], al[1], al[2], al[3], bq[0], bq[1]);
    mma_bf16(a3, al[0], al[1], al[2], al[3], bq[2], bq[3]);
}

// B-tile element offset (bytes): TR=0 -> [n][k] layout; TR=1 -> rows (trans)
template <int TR>
static __device__ __forceinline__ uint32_t boff(int kk, int j) {
    return TR ? (uint32_t)(kk * 16 * PITCH + j * 16) * 2
              : (uint32_t)(j * 16 * PITCH + kk * 16) * 2;
}
template <int TR>
static __device__ __forceinline__ void ldB(uint32_t r[4], uint32_t addr) {
    if (TR)
        ldsm4t(r[0], r[1], r[2], r[3], addr);
    else
        ldsm4(r[0], r[1], r[2], r[3], addr);
}

// Pipelined: acc = A(register frags) @ B(smem), double-buffered B-frags
template <int TR>
static __device__ __forceinline__ void gemm_r(const uint32_t* Ah,
                                              const uint32_t* Al, uint32_t bH,
                                              uint32_t bL, float acc[16][4]) {
    zero_acc(acc);
    uint32_t bp[2][4], cp[2][4], bq[2][4], cq[2][4];
    ldB<TR>(bp[0], bH + boff<TR>(0, 0));
    ldB<TR>(cp[0], bL + boff<TR>(0, 0));
    ldB<TR>(bq[0], bH + boff<TR>(0, 1));
    ldB<TR>(cq[0], bL + boff<TR>(0, 1));
#pragma unroll
    for (int it = 0; it < 32; ++it) {
        const int cur = it & 1, nxt = cur ^ 1;
        if (it < 31) {
            const int kk1 = (it + 1) >> 2, jp1 = (it + 1) & 3;
            ldB<TR>(bp[nxt], bH + boff<TR>(kk1, 2 * jp1));
            ldB<TR>(cp[nxt], bL + boff<TR>(kk1, 2 * jp1));
            ldB<TR>(bq[nxt], bH + boff<TR>(kk1, 2 * jp1 + 1));
            ldB<TR>(cq[nxt], bL + boff<TR>(kk1, 2 * jp1 + 1));
        }
        const int kk = it >> 2, jp = it & 3;
        mma_oct(acc[4 * jp], acc[4 * jp + 1], acc[4 * jp + 2], acc[4 * jp + 3],
                &Ah[4 * kk], &Al[4 * kk], bp[cur], cp[cur], bq[cur], cq[cur]);
    }
}

// Pipelined: acc = A(smem rows) @ B(smem [n][k]), double-buffered A+B frags
static __device__ __forceinline__ void gemm_s(uint32_t aH, uint32_t aL,
                                              uint32_t bH, uint32_t bL,
                                              float acc[16][4]) {
    zero_acc(acc);
    uint32_t ah[2][4], al[2][4];
    uint32_t bp[2][4], cp[2][4], bq[2][4], cq[2][4];
    ldsm4(ah[0][0], ah[0][1], ah[0][2], ah[0][3], aH);
    ldsm4(al[0][0], al[0][1], al[0][2], al[0][3], aL);
    ldB<0>(bp[0], bH + boff<0>(0, 0));
    ldB<0>(cp[0], bL + boff<0>(0, 0));
    ldB<0>(bq[0], bH + boff<0>(0, 1));
    ldB<0>(cq[0], bL + boff<0>(0, 1));
#pragma unroll
    for (int it = 0; it < 32; ++it) {
        const int cur = it & 1, nxt = cur ^ 1;
        if (it < 31) {
            const int kk1 = (it + 1) >> 2, jp1 = (it + 1) & 3;
            if (jp1 == 0) {
                ldsm4(ah[kk1 & 1][0], ah[kk1 & 1][1], ah[kk1 & 1][2],
                      ah[kk1 & 1][3], aH + kk1 * 32);
                ldsm4(al[kk1 & 1][0], al[kk1 & 1][1], al[kk1 & 1][2],
                      al[kk1 & 1][3], aL + kk1 * 32);
            }
            ldB<0>(bp[nxt], bH + boff<0>(kk1, 2 * jp1));
            ldB<0>(cp[nxt], bL + boff<0>(kk1, 2 * jp1));
            ldB<0>(bq[nxt], bH + boff<0>(kk1, 2 * jp1 + 1));
            ldB<0>(cq[nxt], bL + boff<0>(kk1, 2 * jp1 + 1));
        }
        const int kk = it >> 2, jp = it & 3;
        mma_oct(acc[4 * jp], acc[4 * jp + 1], acc[4 * jp + 2], acc[4 * jp + 3],
                ah[kk & 1], al[kk & 1], bp[cur], cp[cur], bq[cur], cq[cur]);
    }
}

// C fragments -> A fragments (hi/lo) of next GEMM
static __device__ __forceinline__ void to_afrag(const float acc[16][4],
                                                uint32_t* Ah, uint32_t* Al) {
#pragma unroll
    for (int kk = 0; kk < 8; ++kk) {
        split2(acc[2 * kk][0], acc[2 * kk][1], Ah[4 * kk + 0], Al[4 * kk + 0]);
        split2(acc[2 * kk][2], acc[2 * kk][3], Ah[4 * kk + 1], Al[4 * kk + 1]);
        split2(acc[2 * kk + 1][0], acc[2 * kk + 1][1], Ah[4 * kk + 2],
               Al[4 * kk + 2]);
        split2(acc[2 * kk + 1][2], acc[2 * kk + 1][3], Ah[4 * kk + 3],
               Al[4 * kk + 3]);
    }
}

// ---------------------------------------------------------------------------
// prep: grid (2, 16), block 256.
//  m=0: B[n][k] = (Wq Wk^T)[k][n] / sqrt(d);  m=1: B[n][k] = (Wv Wo)[k][n]
// ---------------------------------------------------------------------------
__global__ void prep_kernel(const float* __restrict__ Wq,
                            const float* __restrict__ Wk,
                            const float* __restrict__ Wv,
                            const float* __restrict__ Wo) {
    extern __shared__ float ps[];
    float* As = ps;                // 128 x 129 (padded)
    float* Bs = ps + 128 * 129;    // 8 x 128
    const int m = blockIdx.x;
    const int n0 = blockIdx.y * 8;
    const int tid = threadIdx.x;

    const float* A = (m == 0) ? Wq : Wv;
    for (int idx = tid; idx < 16384; idx += 256) {
        int r = idx >> 7, c = idx & 127;
        As[r * 129 + c] = A[idx];
    }
    if (m == 0) {
        for (int idx = tid; idx < 1024; idx += 256)
            Bs[idx] = Wk[n0 * 128 + idx];
    } else {
        for (int idx = tid; idx < 1024; idx += 256) {
            int j = idx >> 7, i = idx & 127;
            Bs[j * 128 + i] = Wo[i * 128 + n0 + j];
        }
    }
    __syncthreads();

    const int k = tid & 127;
    const int jb = tid >> 7;
    const float scale = (m == 0) ? 0.08838834764831845f : 1.0f;
#pragma unroll
    for (int jj = 0; jj < 4; ++jj) {
        int j = jb + 2 * jj;
        float acc = 0.f;
#pragma unroll 8
        for (int i = 0; i < 128; ++i)
            acc = fmaf(As[k * 129 + i], Bs[j * 128 + i], acc);
        acc *= scale;
        __nv_bfloat16 h = __float2bfloat16(acc);
        float r = acc - __bfloat162float(h);
        __nv_bfloat16 l = __float2bfloat16(r);
        int n = n0 + j;
        g_wh[m][n * PITCH + k] = __bfloat16_as_ushort(h);
        g_wl[m][n * PITCH + k] = __bfloat16_as_ushort(l);
    }
}

// ---------------------------------------------------------------------------
// Main fused kernel: one CTA per 128-token block, 256 threads (8 warps).
//   Q2 = X @ M;  V = X @ Wvo;  S = Q2 @ X^T;  P = softmax(S);  H = P @ V
// ---------------------------------------------------------------------------
__global__ void __launch_bounds__(256, 1) attn_kernel(
    const float* __restrict__ x, const float* __restrict__ gamma,
    const float* __restrict__ beta, float* __restrict__ out) {
    extern __shared__ char smc[];
    const int tid = threadIdx.x;
    const int lane = tid & 31;
    const int w = tid >> 5;
    const int g = lane >> 2, t = lane & 3;
    const int R = 16 * w;

    const uint32_t xh_u = smem_u32(smc + XH_OFF);
    const uint32_t xl_u = smem_u32(smc + XL_OFF);
    const uint32_t w1h_u = smem_u32(smc + W1H_OFF);
    const uint32_t w1l_u = smem_u32(smc + W1L_OFF);
    const uint32_t w2h_u = smem_u32(smc + W2H_OFF);
    const uint32_t w2l_u = smem_u32(smc + W2L_OFF);

    const int L = lane;
    const uint32_t offA =
        (uint32_t)(((L & 7) + (L & 8)) * PITCH + ((L & 16) ? 8 : 0)) * 2;
    const uint32_t offB =
        (uint32_t)(((L & 7) + ((L & 16) ? 8 : 0)) * PITCH + (L & 8)) * 2;
    const uint32_t offT =
        (uint32_t)((L & 15) * PITCH + ((L & 16) ? 8 : 0)) * 2;

    // --- async prefetch: M -> W1, Wvo -> W2 ---
    for (int i = tid; i < 2176; i += 256) {
        cp16(w1h_u + i * 16, (const char*)g_wh[0] + i * 16);
        cp16(w1l_u + i * 16, (const char*)g_wl[0] + i * 16);
        cp16(w2h_u + i * 16, (const char*)g_wh[1] + i * 16);
        cp16(w2l_u + i * 16, (const char*)g_wl[1] + i * 16);
    }
    CP_COMMIT();

    float* sgam = (float*)(smc + GB_OFF);
    float* sbet = sgam + 128;
    float* sgel = sgam + 256;
    if (tid < 128) {
        float b = beta[tid];
        sgam[tid] = gamma[tid];
        sbet[tid] = b;
        sgel[tid] = 0.5f * b * (1.f + erff(b * 0.70710678118654752f));
    }

    // --- load X tile -> bf16 hi/lo pitched smem ---
    const int xrow = tid >> 1, xc0 = (tid & 1) * 64;
    {
        unsigned short* XH = (unsigned short*)(smc + XH_OFF);
        unsigned short* XL = (unsigned short*)(smc + XL_OFF);
        const long long base =
            ((long long)blockIdx.y * 8192 + (long long)blockIdx.x * 128) * 128;
        const float4* xg = (const float4*)(x + base + xrow * 128 + xc0);
#pragma unroll
        for (int i = 0; i < 16; ++i) {
            float4 f = xg[i];
            uint32_t h0, l0, h1, l1;
            split2(f.x, f.y, h0, l0);
            split2(f.z, f.w, h1, l1);
            *(uint32_t*)&XH[xrow * PITCH + xc0 + 4 * i] = h0;
            *(uint32_t*)&XH[xrow * PITCH + xc0 + 4 * i + 2] = h1;
            *(uint32_t*)&XL[xrow * PITCH + xc0 + 4 * i] = l0;
            *(uint32_t*)&XL[xrow * PITCH + xc0 + 4 * i + 2] = l1;
        }
    }
    CP_WAIT0();
    __syncthreads();  // X + M + Wvo ready

    // --- mirrored zeros-passer block: out2 = gelu(beta) broadcast ---
    {
        float* o2 = out + (long long)blockIdx.y * 16384 * 128 +
                    ((long long)8192 + blockIdx.x * 128 + xrow) * 128 + xc0;
#pragma unroll
        for (int i = 0; i < 16; ++i)
            *(float4*)(o2 + 4 * i) =
                make_float4(sgel[xc0 + 4 * i], sgel[xc0 + 4 * i + 1],
                            sgel[xc0 + 4 * i + 2], sgel[xc0 + 4 * i + 3]);
    }

    float acc[16][4];
    uint32_t Ah[32], Al[32];
    const uint32_t aH = xh_u + (uint32_t)(R * PITCH) * 2 + offA;
    const uint32_t aL = xl_u + (uint32_t)(R * PITCH) * 2 + offA;

    // ---- Q2 = X @ M ----
    gemm_s(aH, aL, w1h_u + offB, w1l_u + offB, acc);
    to_afrag(acc, Ah, Al);  // Q2 frags

    // ---- V = X @ Wvo (independent; fills the M->V gap) ----
    gemm_s(aH, aL, w2h_u + offB, w2l_u + offB, acc);
    __syncthreads();  // all warps done reading M (W1 recyclable)

    // store V -> W1 region (bf16 hi/lo, row-major [tok][d])
    {
        unsigned short* VH = (unsigned short*)(smc + W1H_OFF);
        unsigned short* VL = (unsigned short*)(smc + W1L_OFF);
#pragma unroll
        for (int j = 0; j < 16; ++j) {
            const int col = 8 * j + 2 * t;
            uint32_t h, l;
            split2(acc[j][0], acc[j][1], h, l);
            *(uint32_t*)&VH[(R + g) * PITCH + col] = h;
            *(uint32_t*)&VL[(R + g) * PITCH + col] = l;
            split2(acc[j][2], acc[j][3], h, l);
            *(uint32_t*)&VH[(R + g + 8) * PITCH + col] = h;
            *(uint32_t*)&VL[(R + g + 8) * PITCH + col] = l;
        }
    }

    // ---- S = Q2 @ X^T (B = X rows, non-trans ldmatrix) ----
    gemm_r<0>(Ah, Al, xh_u + offB, xl_u + offB, acc);

    // ---- softmax per row ----
    {
        float mx0 = -1e30f, mx1 = -1e30f;
#pragma unroll
        for (int j = 0; j < 16; ++j) {
            mx0 = fmaxf(mx0, fmaxf(acc[j][0], acc[j][1]));
            mx1 = fmaxf(mx1, fmaxf(acc[j][2], acc[j][3]));
        }
        mx0 = fmaxf(mx0, __shfl_xor_sync(0xffffffffu, mx0, 1));
        mx0 = fmaxf(mx0, __shfl_xor_sync(0xffffffffu, mx0, 2));
        mx1 = fmaxf(mx1, __shfl_xor_sync(0xffffffffu, mx1, 1));
        mx1 = fmaxf(mx1, __shfl_xor_sync(0xffffffffu, mx1, 2));
        float s0 = 0.f, s1 = 0.f;
#pragma unroll
        for (int j = 0; j < 16; ++j) {
            acc[j][0] = __expf(acc[j][0] - mx0);
            acc[j][1] = __expf(acc[j][1] - mx0);
            acc[j][2] = __expf(acc[j][2] - mx1);
            acc[j][3] = __expf(acc[j][3] - mx1);
            s0 += acc[j][0] + acc[j][1];
            s1 += acc[j][2] + acc[j][3];
        }
        s0 += __shfl_xor_sync(0xffffffffu, s0, 1);
        s0 += __shfl_xor_sync(0xffffffffu, s0, 2);
        s1 += __shfl_xor_sync(0xffffffffu, s1, 1);
        s1 += __shfl_xor_sync(0xffffffffu, s1, 2);
        float i0 = 1.0f / s0, i1 = 1.0f / s1;
#pragma unroll
        for (int j = 0; j < 16; ++j) {
            acc[j][0] *= i0;
            acc[j][1] *= i0;
            acc[j][2] *= i1;
            acc[j][3] *= i1;
        }
    }
    to_afrag(acc, Ah, Al);  // P frags

    __syncthreads();  // V stores visible

    // ---- H = P @ V (ldmatrix.trans on V rows) ----
    gemm_r<1>(Ah, Al, w1h_u + offT, w1l_u + offT, acc);

    // ---- LayerNorm + exact GELU + store ----
    {
        float s0 = 0.f, s1 = 0.f;
#pragma unroll
        for (int j = 0; j < 16; ++j) {
            s0 += acc[j][0] + acc[j][1];
            s1 += acc[j][2] + acc[j][3];
        }
        s0 += __shfl_xor_sync(0xffffffffu, s0, 1);
        s0 += __shfl_xor_sync(0xffffffffu, s0, 2);
        s1 += __shfl_xor_sync(0xffffffffu, s1, 1);
        s1 += __shfl_xor_sync(0xffffffffu, s1, 2);
        float mu0 = s0 * (1.0f / 128.0f), mu1 = s1 * (1.0f / 128.0f);
        float q0 = 0.f, q1 = 0.f;
#pragma unroll
        for (int j = 0; j < 16; ++j) {
            float d0 = acc[j][0] - mu0, d1 = acc[j][1] - mu0;
            float d2 = acc[j][2] - mu1, d3 = acc[j][3] - mu1;
            q0 += d0 * d0 + d1 * d1;
            q1 += d2 * d2 + d3 * d3;
        }
        q0 += __shfl_xor_sync(0xffffffffu, q0, 1);
        q0 += __shfl_xor_sync(0xffffffffu, q0, 2);
        q1 += __shfl_xor_sync(0xffffffffu, q1, 1);
        q1 += __shfl_xor_sync(0xffffffffu, q1, 2);
        float r0 = rsqrtf(q0 * (1.0f / 128.0f) + 1e-5f);
        float r1 = rsqrtf(q1 * (1.0f / 128.0f) + 1e-5f);

        float* orow = out + ((long long)blockIdx.y * 16384 +
                             (long long)blockIdx.x * 128 + R + g) * 128;
        float* orow8 = orow + 8 * 128;
#pragma unroll
        for (int j = 0; j < 16; ++j) {
            const int col = 8 * j + 2 * t;
            float ga0 = sgam[col], ga1 = sgam[col + 1];
            float be0 = sbet[col], be1 = sbet[col + 1];
            float y0 = (acc[j][0] - mu0) * r0 * ga0 + be0;
            float y1 = (acc[j][1] - mu0) * r0 * ga1 + be1;
            float y2 = (acc[j][2] - mu1) * r1 * ga0 + be0;
            float y3 = (acc[j][3] - mu1) * r1 * ga1 + be1;
            float2 o0, o1;
            o0.x = 0.5f * y0 * (1.f + erff(y0 * 0.70710678118654752f));
            o0.y = 0.5f * y1 * (1.f + erff(y1 * 0.70710678118654752f));
            o1.x = 0.5f * y2 * (1.f + erff(y2 * 0.70710678118654752f));
            o1.y = 0.5f * y3 * (1.f + erff(y3 * 0.70710678118654752f));
            *(float2*)&orow[col] = o0;
            *(float2*)&orow8[col] = o1;
        }
    }
}

// ---------------------------------------------------------------------------
extern "C" void kernel_launch(void* const* d_in, const int* in_sizes, int n_in,
                              void* d_out, int out_size) {
    const float* x     = (const float*)d_in[0];
    const float* Wq    = (const float*)d_in[1];
    const float* Wk    = (const float*)d_in[2];
    const float* Wv    = (const float*)d_in[3];
    const float* Wo    = (const float*)d_in[4];
    const float* gamma = (const float*)d_in[5];
    const float* beta  = (const float*)d_in[6];
    float* out = (float*)d_out;

    cudaFuncSetAttribute(attn_kernel,
                         cudaFuncAttributeMaxDynamicSharedMemorySize, SMEM_BYTES);
    cudaFuncSetAttribute(prep_kernel,
                         cudaFuncAttributeMaxDynamicSharedMemorySize, PREP_SMEM);

    prep_kernel<<<dim3(2, 16), 256, PREP_SMEM>>>(Wq, Wk, Wv, Wo);
    attn_kernel<<<dim3(64, 8), 256, SMEM_BYTES>>>(x, gamma, beta, out);
}